// round 15
// baseline (speedup 1.0000x reference)
#include <cuda_runtime.h>

#define KK     3
#define CIN    16
#define COUT   16
#define HH     64
#define WW     64
#define BB     4

#define TILE_H 8          // output rows per block
#define BX     64
#define BY     2          // 128 threads; each thread: 4 rows, 1 packed f-pair
#define PX     4          // pixels (rows) per thread
#define FG     2          // output channels per block
#define CQ     4          // input channels per block (CIN split in 4)

#define SX_ROWS (TILE_H + 2)                 // 10
#define NOUT    (BB * COUT * HH * WW)        // 1,048,576

typedef unsigned long long ull;

// ---------------- Blackwell packed f32x2 helpers ----------------
__device__ __forceinline__ ull pk2s(float v) {            // (v, v)
    ull r; asm("mov.b64 %0, {%1, %1};" : "=l"(r) : "f"(v)); return r;
}
__device__ __forceinline__ void upk2(ull v, float& lo, float& hi) {
    asm("mov.b64 {%0, %1}, %2;" : "=f"(lo), "=f"(hi) : "l"(v));
}
__device__ __forceinline__ ull pk2(float lo, float hi) {
    ull r; asm("mov.b64 %0, {%1, %2};" : "=l"(r) : "f"(lo), "f"(hi)); return r;
}
__device__ __forceinline__ ull ffma2(ull a, ull b, ull c) {
    ull d; asm("fma.rn.f32x2 %0, %1, %2, %3;" : "=l"(d) : "l"(a), "l"(b), "l"(c)); return d;
}
__device__ __forceinline__ ull fmul2(ull a, ull b) {
    ull d; asm("mul.rn.f32x2 %0, %1, %2;" : "=l"(d) : "l"(a), "l"(b)); return d;
}
__device__ __forceinline__ float frcp(float x) {
    float r; asm("rcp.approx.ftz.f32 %0, %1;" : "=f"(r) : "f"(x)); return r;
}
__device__ __forceinline__ void redg_add(float* p, float v) {
    asm volatile("red.global.add.f32 [%0], %1;" :: "l"(p), "f"(v) : "memory");
}

// ---- zero the output buffer (poisoned by harness) ----
__global__ __launch_bounds__(128)
void zero_kernel(float* __restrict__ out) {
    const int i = blockIdx.x * 128 + threadIdx.x;       // float4 index
    reinterpret_cast<float4*>(out)[i] = make_float4(0.f, 0.f, 0.f, 0.f);
}

// Static SMEM (~13.1 KB):
//  sC: packed coefficients, this block's f-pair x its 4 input channels:
//      per (c,p): 10 float2 (6 A-pairs, 4 B-pairs) -> 360 float2 = 2880 B
//  sX: 4 input-channel tiles, 10 rows x 66 cols = 10560 B
__global__ __launch_bounds__(BX * BY, 7)    // 73-reg budget, 7 blocks/SM
void kaconv_kernel(const float* __restrict__ x,
                   const float* __restrict__ A,
                   const float* __restrict__ Bc,
                   float* __restrict__ out) {
    __shared__ __align__(16) ull  sC[CQ * 9 * 10];   // 360 slots = 2880 B
    __shared__ float              sX[CQ * SX_ROWS * 66];

    const int tx  = threadIdx.x;
    const int ty  = threadIdx.y;
    const int tid = ty * BX + tx;
    const int h0  = blockIdx.x * TILE_H;
    const int b   = blockIdx.y;
    const int f0  = (blockIdx.z >> 2) * FG;
    const int cq  = blockIdx.z & 3;            // which c-quarter
    const int c0  = cq * CQ;

    // ---- stage packed coefficients for channels c0..c0+3 ----
    float2* sCf = reinterpret_cast<float2*>(sC);
    for (int i = tid; i < CQ * 9 * 10; i += BX * BY) {
        int ii = i;
        const int k = ii % 10; ii /= 10;
        const int p = ii % 9;
        const int c = c0 + ii / 9;
        float lo, hi;
        if (k < 6) {
            lo = A[(( f0      * CIN + c) * 9 + p) * 6 + k];
            hi = A[(((f0 + 1) * CIN + c) * 9 + p) * 6 + k];
        } else {
            const int j = k - 6;
            lo = Bc[(( f0      * CIN + c) * 9 + p) * 4 + j];
            hi = Bc[(((f0 + 1) * CIN + c) * 9 + p) * 4 + j];
        }
        sCf[i] = make_float2(lo, hi);
    }

    // ---- stage 4 input-channel tiles with zero-padded halo ----
    for (int i = tid; i < CQ * SX_ROWS * 66; i += BX * BY) {
        const int col = i % 66;
        const int r   = (i / 66) % SX_ROWS;
        const int cl  = i / (66 * SX_ROWS);
        const int gh  = h0 + r - 1;
        const int gw  = col - 1;
        float v = 0.0f;
        if (gh >= 0 && gh < HH && gw >= 0 && gw < WW)
            v = x[((b * CIN + c0 + cl) * HH + gh) * WW + gw];
        sX[(cl * SX_ROWS + r) * 66 + col] = v;
    }
    __syncthreads();

    const ulonglong2* sC2 = reinterpret_cast<const ulonglong2*>(sC);
    const float* xbase = sX + PX * ty * 66 + tx;

    ull acc[PX];
    #pragma unroll
    for (int i = 0; i < PX; i++) acc[i] = 0ull;

    #pragma unroll 1
    for (int c = 0; c < CQ; c++) {
        // 6 rows x 3 cols register window covers all 4 pixels' 3x3 windows
        float xr[PX + 2][3];
        #pragma unroll
        for (int r = 0; r < PX + 2; r++)
            #pragma unroll
            for (int j = 0; j < 3; j++)
                xr[r][j] = xbase[(c * SX_ROWS + r) * 66 + j];

        const ulonglong2* pc = sC2 + c * 45;   // 5 ulonglong2 per (c,p)
        #pragma unroll
        for (int p = 0; p < 9; p++) {
            const int di = p / 3, dj = p % 3;
            const ulonglong2 u0 = pc[p * 5 + 0];  // {A0, A1}
            const ulonglong2 u1 = pc[p * 5 + 1];  // {A2, A3}
            const ulonglong2 u2 = pc[p * 5 + 2];  // {A4, A5}
            const ulonglong2 u3 = pc[p * 5 + 3];  // {B1, B2}
            const ulonglong2 u4 = pc[p * 5 + 4];  // {B3, B4}

            #pragma unroll
            for (int py = 0; py < PX; py++) {
                const ull X = pk2s(xr[py + di][dj]);

                // P = a0 + ... + a5 x^5 (Horner, packed over f-pair)
                ull P = ffma2(u2.y, X, u2.x);
                P = ffma2(P, X, u1.y);
                P = ffma2(P, X, u1.x);
                P = ffma2(P, X, u0.y);
                P = ffma2(P, X, u0.x);

                // S = x*(b1 + x*(b2 + x*(b3 + x*b4)))
                ull T = ffma2(u4.y, X, u4.x);
                T = ffma2(T, X, u3.y);
                T = ffma2(T, X, u3.x);
                T = fmul2(T, X);

                // Denominators q0,q1; ONE reciprocal via product identity:
                //   inv = 1/(q0*q1);  1/q0 = q1*inv;  1/q1 = q0*inv
                // (halves MUFU pressure; +3 FMUL on the fma pipe)
                float t0, t1; upk2(T, t0, t1);
                const float q0 = 1.0f + fabsf(t0);
                const float q1 = 1.0f + fabsf(t1);
                const float inv = frcp(q0 * q1);
                const ull R = pk2(q1 * inv, q0 * inv);

                acc[py] = ffma2(P, R, acc[py]);
            }
        }
    }

    // ---- accumulate into out via fire-and-forget global reductions ----
    // out starts at 0; four contributions per element (one per c-quarter).
    const int hA = h0 + PX * ty;
    const int w  = tx;
    float* op = out + ((b * COUT + f0) * HH + hA) * WW + w;
    #pragma unroll
    for (int py = 0; py < PX; py++) {
        float lo, hi;
        upk2(acc[py], lo, hi);
        redg_add(op + py * WW,           lo);
        redg_add(op + HH * WW + py * WW, hi);
    }
}

extern "C" void kernel_launch(void* const* d_in, const int* in_sizes, int n_in,
                              void* d_out, int out_size) {
    const float* x  = (const float*)d_in[0];
    const float* A  = (const float*)d_in[1];
    const float* Bc = (const float*)d_in[2];
    float* out = (float*)d_out;

    zero_kernel<<<(NOUT / 4) / 128, 128>>>(out);    // 2048 blocks, 4 MB zeros

    dim3 grid(HH / TILE_H, BB, (COUT / FG) * (CIN / CQ));  // (8,4,32) = 1024 blocks
    dim3 block(BX, BY, 1);                                  // 128 threads
    kaconv_kernel<<<grid, block>>>(x, A, Bc, out);
}

// round 16
// speedup vs baseline: 1.1849x; 1.1849x over previous
#include <cuda_runtime.h>

#define KK     3
#define CIN    16
#define COUT   16
#define HH     64
#define WW     64
#define BB     4

#define TILE_H 8          // output rows per block
#define BX     64
#define BY     2          // 128 threads; each thread: 4 rows, 1 packed f-pair
#define PX     4          // pixels (rows) per thread
#define FG     2          // output channels per block
#define CQ     4          // input channels per block (CIN split in 4)

#define SX_ROWS (TILE_H + 2)                 // 10
#define NOUT    (BB * COUT * HH * WW)        // 262,144

typedef unsigned long long ull;

// ---------------- Blackwell packed f32x2 helpers ----------------
__device__ __forceinline__ ull pk2s(float v) {            // (v, v)
    ull r; asm("mov.b64 %0, {%1, %1};" : "=l"(r) : "f"(v)); return r;
}
__device__ __forceinline__ void upk2(ull v, float& lo, float& hi) {
    asm("mov.b64 {%0, %1}, %2;" : "=f"(lo), "=f"(hi) : "l"(v));
}
__device__ __forceinline__ ull pk2(float lo, float hi) {
    ull r; asm("mov.b64 %0, {%1, %2};" : "=l"(r) : "f"(lo), "f"(hi)); return r;
}
__device__ __forceinline__ ull ffma2(ull a, ull b, ull c) {
    ull d; asm("fma.rn.f32x2 %0, %1, %2, %3;" : "=l"(d) : "l"(a), "l"(b), "l"(c)); return d;
}
__device__ __forceinline__ ull fmul2(ull a, ull b) {
    ull d; asm("mul.rn.f32x2 %0, %1, %2;" : "=l"(d) : "l"(a), "l"(b)); return d;
}
__device__ __forceinline__ float frcp(float x) {
    float r; asm("rcp.approx.ftz.f32 %0, %1;" : "=f"(r) : "f"(x)); return r;
}
__device__ __forceinline__ void redg_add(float* p, float v) {
    asm volatile("red.global.add.f32 [%0], %1;" :: "l"(p), "f"(v) : "memory");
}

// ---- zero the output buffer (poisoned by harness) ----
__global__ __launch_bounds__(128)
void zero_kernel(float* __restrict__ out) {
    const int i = blockIdx.x * 128 + threadIdx.x;       // float4 index
    reinterpret_cast<float4*>(out)[i] = make_float4(0.f, 0.f, 0.f, 0.f);
}

// Static SMEM (~13.1 KB):
//  sC: packed coefficients, this block's f-pair x its 4 input channels:
//      per (c,p): 10 float2 (6 A-pairs, 4 B-pairs) -> 360 float2 = 2880 B
//  sX: 4 input-channel tiles, 10 rows x 66 cols = 10560 B
__global__ __launch_bounds__(BX * BY, 7)    // 73-reg budget, 7 blocks/SM
void kaconv_kernel(const float* __restrict__ x,
                   const float* __restrict__ A,
                   const float* __restrict__ Bc,
                   float* __restrict__ out) {
    __shared__ __align__(16) ull  sC[CQ * 9 * 10];   // 360 slots = 2880 B
    __shared__ float              sX[CQ * SX_ROWS * 66];

    const int tx  = threadIdx.x;
    const int ty  = threadIdx.y;
    const int tid = ty * BX + tx;
    const int h0  = blockIdx.x * TILE_H;
    const int b   = blockIdx.y;
    const int f0  = (blockIdx.z >> 2) * FG;
    const int cq  = blockIdx.z & 3;            // which c-quarter
    const int c0  = cq * CQ;

    // ---- stage packed coefficients for channels c0..c0+3 ----
    float2* sCf = reinterpret_cast<float2*>(sC);
    for (int i = tid; i < CQ * 9 * 10; i += BX * BY) {
        int ii = i;
        const int k = ii % 10; ii /= 10;
        const int p = ii % 9;
        const int c = c0 + ii / 9;
        float lo, hi;
        if (k < 6) {
            lo = A[(( f0      * CIN + c) * 9 + p) * 6 + k];
            hi = A[(((f0 + 1) * CIN + c) * 9 + p) * 6 + k];
        } else {
            const int j = k - 6;
            lo = Bc[(( f0      * CIN + c) * 9 + p) * 4 + j];
            hi = Bc[(((f0 + 1) * CIN + c) * 9 + p) * 4 + j];
        }
        sCf[i] = make_float2(lo, hi);
    }

    // ---- stage 4 input-channel tiles (optimized) ----
    // Side halo columns gw=-1 (col 0) and gw=64 (col 65) are ALWAYS outside
    // the image (blocks span the full row) -> constant zero, no loads.
    if (tid < 80) {                              // 40 rows x 2 side cols
        const int row  = tid >> 1;               // 0..39 = cl*10 + r
        const int side = (tid & 1) * 65;         // col 0 or 65
        sX[row * 66 + side] = 0.0f;
    }
    // Interior + vertical halo: 40 rows x 16 aligned float4 quads = 640 units;
    // exactly 5 per thread, shift/mask addressing, one gh bounds predicate.
    #pragma unroll
    for (int k = 0; k < 5; k++) {
        const int unit = tid + k * 128;          // 0..639
        const int row  = unit >> 4;              // 0..39 = cl*10 + r
        const int quad = unit & 15;              // 0..15 (gw = 4*quad..)
        const int cl   = row / 10;               // small magic div
        const int r    = row - cl * 10;
        const int gh   = h0 + r - 1;
        float4 v = make_float4(0.f, 0.f, 0.f, 0.f);
        if ((unsigned)gh < (unsigned)HH)
            v = *reinterpret_cast<const float4*>(
                    &x[(((b * CIN + c0 + cl) * HH + gh) << 6) + (quad << 2)]);
        float* dst = &sX[row * 66 + 1 + (quad << 2)];
        dst[0] = v.x; dst[1] = v.y; dst[2] = v.z; dst[3] = v.w;
    }
    __syncthreads();

    const ulonglong2* sC2 = reinterpret_cast<const ulonglong2*>(sC);
    const float* xbase = sX + PX * ty * 66 + tx;

    ull acc[PX];
    #pragma unroll
    for (int i = 0; i < PX; i++) acc[i] = 0ull;

    #pragma unroll 1
    for (int c = 0; c < CQ; c++) {
        // 6 rows x 3 cols register window covers all 4 pixels' 3x3 windows
        float xr[PX + 2][3];
        #pragma unroll
        for (int r = 0; r < PX + 2; r++)
            #pragma unroll
            for (int j = 0; j < 3; j++)
                xr[r][j] = xbase[(c * SX_ROWS + r) * 66 + j];

        const ulonglong2* pc = sC2 + c * 45;   // 5 ulonglong2 per (c,p)
        #pragma unroll
        for (int p = 0; p < 9; p++) {
            const int di = p / 3, dj = p % 3;
            const ulonglong2 u0 = pc[p * 5 + 0];  // {A0, A1}
            const ulonglong2 u1 = pc[p * 5 + 1];  // {A2, A3}
            const ulonglong2 u2 = pc[p * 5 + 2];  // {A4, A5}
            const ulonglong2 u3 = pc[p * 5 + 3];  // {B1, B2}
            const ulonglong2 u4 = pc[p * 5 + 4];  // {B3, B4}

            #pragma unroll
            for (int py = 0; py < PX; py++) {
                const ull X = pk2s(xr[py + di][dj]);

                // P = a0 + ... + a5 x^5 (Horner, packed over f-pair)
                ull P = ffma2(u2.y, X, u2.x);
                P = ffma2(P, X, u1.y);
                P = ffma2(P, X, u1.x);
                P = ffma2(P, X, u0.y);
                P = ffma2(P, X, u0.x);

                // S = x*(b1 + x*(b2 + x*(b3 + x*b4)))
                ull T = ffma2(u4.y, X, u4.x);
                T = ffma2(T, X, u3.y);
                T = ffma2(T, X, u3.x);
                T = fmul2(T, X);

                // Q = 1 + |S| (abs free on FADD); R = 1/Q via MUFU
                float t0, t1; upk2(T, t0, t1);
                const ull R = pk2(frcp(1.0f + fabsf(t0)), frcp(1.0f + fabsf(t1)));

                acc[py] = ffma2(P, R, acc[py]);
            }
        }
    }

    // ---- accumulate into out via fire-and-forget global reductions ----
    // out starts at 0; four contributions per element (one per c-quarter).
    const int hA = h0 + PX * ty;
    const int w  = tx;
    float* op = out + ((b * COUT + f0) * HH + hA) * WW + w;
    #pragma unroll
    for (int py = 0; py < PX; py++) {
        float lo, hi;
        upk2(acc[py], lo, hi);
        redg_add(op + py * WW,           lo);
        redg_add(op + HH * WW + py * WW, hi);
    }
}

extern "C" void kernel_launch(void* const* d_in, const int* in_sizes, int n_in,
                              void* d_out, int out_size) {
    const float* x  = (const float*)d_in[0];
    const float* A  = (const float*)d_in[1];
    const float* Bc = (const float*)d_in[2];
    float* out = (float*)d_out;

    zero_kernel<<<(NOUT / 4) / 128, 128>>>(out);    // 512 blocks, 1 MB zeros

    dim3 grid(HH / TILE_H, BB, (COUT / FG) * (CIN / CQ));  // (8,4,32) = 1024 blocks
    dim3 block(BX, BY, 1);                                  // 128 threads
    kaconv_kernel<<<grid, block>>>(x, A, Bc, out);
}